// round 4
// baseline (speedup 1.0000x reference)
#include <cuda_runtime.h>
#include <mma.h>
using namespace nvcuda;

// Problem constants
#define NN 50000
#define EE 800000
#define FF 128
#define HH 256
#define GG 512
#define TT 4

// ---------------- scratch (device globals) ----------------------------------
__device__ __align__(16) float g_dinv[NN];
__device__ __align__(16) float g_buf1[(size_t)NN * HH];
__device__ __align__(16) float g_buf2[(size_t)NN * HH];
__device__ __align__(16) float g_sums[GG * HH];
__device__ int g_deg[NN];
__device__ int g_rowstart[NN + 1];
__device__ int g_cursor[NN];
__device__ int g_csr[EE];
__device__ int g_gcnt[GG];
__device__ int g_goff[GG + 1];

// ---------------- small helpers ---------------------------------------------
static __device__ __forceinline__ float4 f4scale(float4 v, float s) {
    return make_float4(v.x * s, v.y * s, v.z * s, v.w * s);
}
static __device__ __forceinline__ void f4fma(float4& a, float4 v, float s) {
    a.x += v.x * s; a.y += v.y * s; a.z += v.z * s; a.w += v.w * s;
}

// ---------------- degree / counts -------------------------------------------
__global__ void k_zero_counts() {
    int i = blockIdx.x * blockDim.x + threadIdx.x;
    if (i < NN) g_deg[i] = 0;
    if (i < GG) g_gcnt[i] = 0;
}

__global__ void k_deg(const int* __restrict__ ei) {
    int e = blockIdx.x * blockDim.x + threadIdx.x;
    if (e < EE) atomicAdd(&g_deg[ei[EE + e]], 1);
}

__global__ void k_ghist(const int* __restrict__ batch) {
    int n = blockIdx.x * blockDim.x + threadIdx.x;
    if (n < NN) atomicAdd(&g_gcnt[batch[n]], 1);
}

__global__ void k_fin_dinv() {
    int n = blockIdx.x * blockDim.x + threadIdx.x;
    if (n < NN) g_dinv[n] = rsqrtf((float)(g_deg[n] + 1));  // +1 self loop
}

// ---------------- one-block scans --------------------------------------------
__global__ void k_scan_nodes() {
    __shared__ int ssum[1024];
    int t = threadIdx.x;
    const int CH = (NN + 1023) / 1024;  // 49
    int lo = t * CH, hi = min(lo + CH, NN);
    int s = 0;
    for (int i = lo; i < hi; i++) s += g_deg[i];
    ssum[t] = s;
    __syncthreads();
    for (int off = 1; off < 1024; off <<= 1) {
        int v = (t >= off) ? ssum[t - off] : 0;
        __syncthreads();
        ssum[t] += v;
        __syncthreads();
    }
    int run = (t > 0) ? ssum[t - 1] : 0;
    for (int i = lo; i < hi; i++) {
        g_rowstart[i] = run;
        g_cursor[i] = run;
        run += g_deg[i];
    }
    if (t == 0) g_rowstart[NN] = EE;
}

__global__ void k_scan_graphs() {
    __shared__ int s[GG];
    int t = threadIdx.x;
    int mine = g_gcnt[t];
    s[t] = mine;
    __syncthreads();
    for (int off = 1; off < GG; off <<= 1) {
        int v = (t >= off) ? s[t - off] : 0;
        __syncthreads();
        s[t] += v;
        __syncthreads();
    }
    g_goff[t] = s[t] - mine;  // exclusive
    if (t == 0) g_goff[GG] = NN;
}

__global__ void k_scatter(const int* __restrict__ ei) {
    int e = blockIdx.x * blockDim.x + threadIdx.x;
    if (e >= EE) return;
    int d = ei[EE + e];
    int p = atomicAdd(&g_cursor[d], 1);
    g_csr[p] = ei[e];
}

// ---------------- CSR aggregation: one warp per dst node --------------------
// out[d] = dinv[d] * ( in[d]*dinv[d] + sum_{s in nbr(d)} in[s]*dinv[s] )
template<int F4>   // F4 = DIM/128 (float4s per lane): 1 for 128-dim, 2 for 256-dim
__global__ void k_agg_csr(const float* __restrict__ in, float* __restrict__ out) {
    int w = (blockIdx.x * blockDim.x + threadIdx.x) >> 5;
    if (w >= NN) return;
    int lane = threadIdx.x & 31;
    const int DIM = F4 * 128;

    float dd = g_dinv[w];
    float4 acc[F4];
    const float4* self = (const float4*)(in + (size_t)w * DIM);
#pragma unroll
    for (int i = 0; i < F4; i++) acc[i] = f4scale(self[lane + i * 32], dd);

    int e = g_rowstart[w];
    int e1 = g_rowstart[w + 1];
    for (; e + 1 < e1; e += 2) {
        int s0 = g_csr[e], s1 = g_csr[e + 1];
        float d0 = g_dinv[s0], d1 = g_dinv[s1];
        const float4* r0 = (const float4*)(in + (size_t)s0 * DIM);
        const float4* r1 = (const float4*)(in + (size_t)s1 * DIM);
#pragma unroll
        for (int i = 0; i < F4; i++) {
            float4 v0 = r0[lane + i * 32];
            float4 v1 = r1[lane + i * 32];
            f4fma(acc[i], v0, d0);
            f4fma(acc[i], v1, d1);
        }
    }
    if (e < e1) {
        int s0 = g_csr[e];
        float d0 = g_dinv[s0];
        const float4* r0 = (const float4*)(in + (size_t)s0 * DIM);
#pragma unroll
        for (int i = 0; i < F4; i++) f4fma(acc[i], r0[lane + i * 32], d0);
    }

    float4* o = (float4*)(out + (size_t)w * DIM);
#pragma unroll
    for (int i = 0; i < F4; i++) o[lane + i * 32] = f4scale(acc[i], dd);
}

// ---------------- TF32 tensor-core GEMM: C = relu(A[M,K] @ B[K,256] + bias) --
// BM=128, BN=64, BK=32. 256 threads = 8 warps (4m x 2n), each warp 32x32.
template<int K>
__global__ void __launch_bounds__(256) k_gemm_tc(
    const float* __restrict__ A, const float* __restrict__ B,
    const float* __restrict__ bias, float* __restrict__ C)
{
    constexpr int BM = 128, BN = 64, BK = 32;
    constexpr int LDA = BK + 4;   // 36
    constexpr int LDB = BN + 8;   // 72
    constexpr int LDC = BN + 8;   // 72

    __shared__ __align__(16) float smem[BM * LDC];   // 128*72 = 9216 floats (36.9 KB)
    float (*As)[LDA] = reinterpret_cast<float(*)[LDA]>(smem);                 // 128*36 = 4608
    float (*Bs)[LDB] = reinterpret_cast<float(*)[LDB]>(smem + BM * LDA);      // 32*72  = 2304
    float (*Cs)[LDC] = reinterpret_cast<float(*)[LDC]>(smem);

    const int tid = threadIdx.x;
    const int warp = tid >> 5;
    const int wm = warp & 3;    // 0..3
    const int wn = warp >> 2;   // 0..1
    const int m0 = blockIdx.y * BM;
    const int n0 = blockIdx.x * BN;

    wmma::fragment<wmma::accumulator, 16, 16, 8, float> acc[2][2];
#pragma unroll
    for (int i = 0; i < 2; i++)
#pragma unroll
        for (int j = 0; j < 2; j++) wmma::fill_fragment(acc[i][j], 0.0f);

    for (int k0 = 0; k0 < K; k0 += BK) {
        // load A tile: 128x32 = 1024 float4s, 4 per thread
#pragma unroll
        for (int i = 0; i < 4; i++) {
            int idx = tid + i * 256;
            int r = idx >> 3;
            int c4 = (idx & 7) * 4;
            float4 v = make_float4(0.f, 0.f, 0.f, 0.f);
            if (m0 + r < NN)
                v = *(const float4*)(A + (size_t)(m0 + r) * K + k0 + c4);
            *(float4*)&As[r][c4] = v;
        }
        // load B tile: 32x64 = 512 float4s, 2 per thread
#pragma unroll
        for (int i = 0; i < 2; i++) {
            int idx = tid + i * 256;
            int r = idx >> 4;
            int c4 = (idx & 15) * 4;
            *(float4*)&Bs[r][c4] = *(const float4*)(B + (size_t)(k0 + r) * HH + n0 + c4);
        }
        __syncthreads();

#pragma unroll
        for (int kk = 0; kk < BK; kk += 8) {
            wmma::fragment<wmma::matrix_a, 16, 16, 8, wmma::precision::tf32, wmma::row_major> fa[2];
            wmma::fragment<wmma::matrix_b, 16, 16, 8, wmma::precision::tf32, wmma::row_major> fb[2];
#pragma unroll
            for (int i = 0; i < 2; i++) {
                wmma::load_matrix_sync(fa[i], &As[wm * 32 + i * 16][kk], LDA);
#pragma unroll
                for (int t = 0; t < fa[i].num_elements; t++)
                    fa[i].x[t] = wmma::__float_to_tf32(fa[i].x[t]);
            }
#pragma unroll
            for (int j = 0; j < 2; j++) {
                wmma::load_matrix_sync(fb[j], &Bs[kk][wn * 32 + j * 16], LDB);
#pragma unroll
                for (int t = 0; t < fb[j].num_elements; t++)
                    fb[j].x[t] = wmma::__float_to_tf32(fb[j].x[t]);
            }
#pragma unroll
            for (int i = 0; i < 2; i++)
#pragma unroll
                for (int j = 0; j < 2; j++)
                    wmma::mma_sync(acc[i][j], fa[i], fb[j], acc[i][j]);
        }
        __syncthreads();
    }

    // stage accumulators to smem, then bias + relu + guarded store
#pragma unroll
    for (int i = 0; i < 2; i++)
#pragma unroll
        for (int j = 0; j < 2; j++)
            wmma::store_matrix_sync(&Cs[wm * 32 + i * 16][wn * 32 + j * 16],
                                    acc[i][j], LDC, wmma::mem_row_major);
    __syncthreads();

#pragma unroll
    for (int i = 0; i < 8; i++) {
        int idx = tid + i * 256;           // 0..2047 (128 rows x 16 float4)
        int r = idx >> 4;
        int c4 = (idx & 15) * 4;
        int m = m0 + r;
        if (m < NN) {
            float4 v = *(const float4*)&Cs[r][c4];
            float4 b = *(const float4*)(bias + n0 + c4);
            v.x = fmaxf(v.x + b.x, 0.0f);
            v.y = fmaxf(v.y + b.y, 0.0f);
            v.z = fmaxf(v.z + b.z, 0.0f);
            v.w = fmaxf(v.w + b.w, 0.0f);
            *(float4*)(C + (size_t)m * HH + n0 + c4) = v;
        }
    }
}

// ---------------- segmented pool: one block per graph ------------------------
__global__ void k_pool_seg(const float* __restrict__ in) {
    int g = blockIdx.x;
    int c = threadIdx.x;                 // 256
    int lo = g_goff[g], hi = g_goff[g + 1];
    float acc = 0.0f;
    for (int n = lo; n < hi; n++) acc += in[(size_t)n * HH + c];
    g_sums[g * HH + c] = acc;
}

// ---------------- MLP head ----------------------------------------------------
__global__ void k_head(const float* __restrict__ na,
                       const float* __restrict__ W3, const float* __restrict__ b3,
                       const float* __restrict__ W4, const float* __restrict__ b4,
                       float* __restrict__ out) {
    int g = blockIdx.x;
    int j = threadIdx.x;   // 32 threads
    __shared__ float zsh[32];

    float cnt = (float)(g_goff[g + 1] - g_goff[g]);
    float inv = 1.0f / fmaxf(cnt, 1.0f);
    float acc = b3[j];
#pragma unroll 8
    for (int k = 0; k < HH; k++)
        acc += (g_sums[g * HH + k] * inv) * W3[k * 32 + j];
    acc += na[g] * W3[HH * 32 + j];
    zsh[j] = fmaxf(acc, 0.0f);
    __syncthreads();

    if (j < TT) {
        float o = b4[j];
#pragma unroll
        for (int t = 0; t < 32; t++) o += zsh[t] * W4[t * TT + j];
        out[g * TT + j] = o;
    }
}

// ---------------- launch -----------------------------------------------------
extern "C" void kernel_launch(void* const* d_in, const int* in_sizes, int n_in,
                              void* d_out, int out_size) {
    const float* x     = (const float*)d_in[0];
    const int*   ei    = (const int*)  d_in[1];
    const int*   batch = (const int*)  d_in[2];
    const float* na    = (const float*)d_in[3];
    const float* W1    = (const float*)d_in[4];
    const float* b1    = (const float*)d_in[5];
    const float* W2    = (const float*)d_in[6];
    const float* b2    = (const float*)d_in[7];
    const float* W3    = (const float*)d_in[8];
    const float* b3    = (const float*)d_in[9];
    const float* W4    = (const float*)d_in[10];
    const float* b4    = (const float*)d_in[11];
    float* out = (float*)d_out;

    // CSR build + normalization
    k_zero_counts<<<(NN + 255) / 256, 256>>>();
    k_deg<<<(EE + 255) / 256, 256>>>(ei);
    k_ghist<<<(NN + 255) / 256, 256>>>(batch);
    k_fin_dinv<<<(NN + 255) / 256, 256>>>();
    k_scan_nodes<<<1, 1024>>>();
    k_scan_graphs<<<1, GG>>>();
    k_scatter<<<(EE + 255) / 256, 256>>>(ei);

    const int agg_blocks = (NN * 32 + 255) / 256;
    dim3 gemm_grid(HH / 64, (NN + 127) / 128);

    // Layer 1: aggregate x (128-dim) first, then GEMM with fused bias+relu
    k_agg_csr<1><<<agg_blocks, 256>>>(x, g_buf2);
    k_gemm_tc<FF><<<gemm_grid, 256>>>(g_buf2, W1, b1, g_buf1);

    // Layer 2: aggregate h1 (256-dim), then GEMM with fused bias+relu
    k_agg_csr<2><<<agg_blocks, 256>>>(g_buf1, g_buf2);
    k_gemm_tc<HH><<<gemm_grid, 256>>>(g_buf2, W2, b2, g_buf1);

    // Pool + head
    k_pool_seg<<<GG, HH>>>(g_buf1);
    k_head<<<GG, 32>>>(na, W3, b3, W4, b4, out);
}

// round 5
// speedup vs baseline: 1.0208x; 1.0208x over previous
#include <cuda_runtime.h>

// Problem constants
#define NN 50000
#define EE 800000
#define FF 128
#define HH 256
#define GG 512
#define TT 4

// ---------------- scratch (device globals) ----------------------------------
__device__ __align__(16) float g_dinv[NN];
__device__ __align__(16) float g_buf1[(size_t)NN * HH];
__device__ __align__(16) float g_buf2[(size_t)NN * HH];
__device__ __align__(16) float g_sums[GG * HH];
__device__ int g_deg[NN];
__device__ int g_rowstart[NN + 1];
__device__ int g_cursor[NN];
__device__ int g_csr[EE];
__device__ int g_gcnt[GG];
__device__ int g_goff[GG + 1];

// ---------------- small helpers ---------------------------------------------
static __device__ __forceinline__ float4 f4scale(float4 v, float s) {
    return make_float4(v.x * s, v.y * s, v.z * s, v.w * s);
}
static __device__ __forceinline__ void f4fma(float4& a, float4 v, float s) {
    a.x += v.x * s; a.y += v.y * s; a.z += v.z * s; a.w += v.w * s;
}
static __device__ __forceinline__ unsigned long long pack2(float lo, float hi) {
    unsigned long long r;
    asm("mov.b64 %0, {%1, %2};" : "=l"(r) : "f"(lo), "f"(hi));
    return r;
}
static __device__ __forceinline__ void fma_f32x2(unsigned long long& acc,
                                                 unsigned long long a,
                                                 unsigned long long b) {
    asm("fma.rn.f32x2 %0, %1, %2, %0;" : "+l"(acc) : "l"(a), "l"(b));
}

// ---------------- degree / counts -------------------------------------------
__global__ void k_zero_counts() {
    int i = blockIdx.x * blockDim.x + threadIdx.x;
    if (i < NN) g_deg[i] = 0;
    if (i < GG) g_gcnt[i] = 0;
}

__global__ void k_deg(const int* __restrict__ ei) {
    int e = blockIdx.x * blockDim.x + threadIdx.x;
    if (e < EE) atomicAdd(&g_deg[ei[EE + e]], 1);
}

__global__ void k_ghist(const int* __restrict__ batch) {
    int n = blockIdx.x * blockDim.x + threadIdx.x;
    if (n < NN) atomicAdd(&g_gcnt[batch[n]], 1);
}

__global__ void k_fin_dinv() {
    int n = blockIdx.x * blockDim.x + threadIdx.x;
    if (n < NN) g_dinv[n] = rsqrtf((float)(g_deg[n] + 1));  // +1 self loop
}

// ---------------- one-block scans --------------------------------------------
__global__ void k_scan_nodes() {
    __shared__ int ssum[1024];
    int t = threadIdx.x;
    const int CH = (NN + 1023) / 1024;
    int lo = t * CH, hi = min(lo + CH, NN);
    int s = 0;
    for (int i = lo; i < hi; i++) s += g_deg[i];
    ssum[t] = s;
    __syncthreads();
    for (int off = 1; off < 1024; off <<= 1) {
        int v = (t >= off) ? ssum[t - off] : 0;
        __syncthreads();
        ssum[t] += v;
        __syncthreads();
    }
    int run = (t > 0) ? ssum[t - 1] : 0;
    for (int i = lo; i < hi; i++) {
        g_rowstart[i] = run;
        g_cursor[i] = run;
        run += g_deg[i];
    }
    if (t == 0) g_rowstart[NN] = EE;
}

__global__ void k_scan_graphs() {
    __shared__ int s[GG];
    int t = threadIdx.x;
    int mine = g_gcnt[t];
    s[t] = mine;
    __syncthreads();
    for (int off = 1; off < GG; off <<= 1) {
        int v = (t >= off) ? s[t - off] : 0;
        __syncthreads();
        s[t] += v;
        __syncthreads();
    }
    g_goff[t] = s[t] - mine;
    if (t == 0) g_goff[GG] = NN;
}

__global__ void k_scatter(const int* __restrict__ ei) {
    int e = blockIdx.x * blockDim.x + threadIdx.x;
    if (e >= EE) return;
    int d = ei[EE + e];
    int p = atomicAdd(&g_cursor[d], 1);
    g_csr[p] = ei[e];
}

// ---------------- CSR aggregation: one warp per dst node --------------------
template<int F4>   // F4 = DIM/128
__global__ void k_agg_csr(const float* __restrict__ in, float* __restrict__ out) {
    int w = (blockIdx.x * blockDim.x + threadIdx.x) >> 5;
    if (w >= NN) return;
    int lane = threadIdx.x & 31;
    const int DIM = F4 * 128;

    float dd = g_dinv[w];
    float4 acc[F4];
    const float4* self = (const float4*)(in + (size_t)w * DIM);
#pragma unroll
    for (int i = 0; i < F4; i++) acc[i] = f4scale(self[lane + i * 32], dd);

    int e = g_rowstart[w];
    int e1 = g_rowstart[w + 1];
    for (; e + 1 < e1; e += 2) {
        int s0 = g_csr[e], s1 = g_csr[e + 1];
        float d0 = g_dinv[s0], d1 = g_dinv[s1];
        const float4* r0 = (const float4*)(in + (size_t)s0 * DIM);
        const float4* r1 = (const float4*)(in + (size_t)s1 * DIM);
#pragma unroll
        for (int i = 0; i < F4; i++) {
            float4 v0 = r0[lane + i * 32];
            float4 v1 = r1[lane + i * 32];
            f4fma(acc[i], v0, d0);
            f4fma(acc[i], v1, d1);
        }
    }
    if (e < e1) {
        int s0 = g_csr[e];
        float d0 = g_dinv[s0];
        const float4* r0 = (const float4*)(in + (size_t)s0 * DIM);
#pragma unroll
        for (int i = 0; i < F4; i++) f4fma(acc[i], r0[lane + i * 32], d0);
    }

    float4* o = (float4*)(out + (size_t)w * DIM);
#pragma unroll
    for (int i = 0; i < F4; i++) o[lane + i * 32] = f4scale(acc[i], dd);
}

// ---------------- f32x2 SGEMM: C = relu(A[M,K] @ B[K,256] + bias) -----------
// BM=128, BN=128, BK=16, 256 threads, 8x8 microtile, paired-FMA (fma.rn.f32x2).
// Accumulator pairs are along M so A pairs come free from LDS.128 aliasing.
union F4U { float4 f4; struct { unsigned long long lo, hi; } u; };

template<int K>
__global__ void __launch_bounds__(256, 2) k_gemm_f2(
    const float* __restrict__ A, const float* __restrict__ B,
    const float* __restrict__ bias, float* __restrict__ C)
{
    constexpr int BM = 128, BN = 128, BK = 16;
    __shared__ __align__(16) float As[BK][BM];   // 8 KB (transposed)
    __shared__ __align__(16) float Bs[BK][BN];   // 8 KB

    const int tid = threadIdx.x;
    const int tx = tid & 15;          // col group: 8 cols
    const int ty = tid >> 4;          // row group: 8 rows
    const int m0 = blockIdx.y * BM;
    const int n0 = blockIdx.x * BN;

    // acc[i2][j] = ( C[2*i2][j], C[2*i2+1][j] ) packed
    unsigned long long acc[4][8];
#pragma unroll
    for (int i = 0; i < 4; i++)
#pragma unroll
        for (int j = 0; j < 8; j++) acc[i][j] = 0ULL;

    // loader mappings
    const int ar = tid >> 2;          // 0..63 base A row (x2 iters -> 128 rows)
    const int ak = (tid & 3) * 4;     // k offset 0,4,8,12
    const int br = tid >> 5;          // 0..7 base B row (x2 iters -> 16 rows)
    const int bc = (tid & 31) * 4;    // col 0..124

    for (int k0 = 0; k0 < K; k0 += BK) {
#pragma unroll
        for (int it = 0; it < 2; it++) {
            int r = ar + it * 64;
            float4 v = make_float4(0.f, 0.f, 0.f, 0.f);
            if (m0 + r < NN)
                v = *(const float4*)(A + (size_t)(m0 + r) * K + k0 + ak);
            As[ak + 0][r] = v.x;
            As[ak + 1][r] = v.y;
            As[ak + 2][r] = v.z;
            As[ak + 3][r] = v.w;
        }
#pragma unroll
        for (int it = 0; it < 2; it++) {
            int r = br + it * 8;
            *(float4*)&Bs[r][bc] = *(const float4*)(B + (size_t)(k0 + r) * HH + n0 + bc);
        }
        __syncthreads();

#pragma unroll
        for (int kk = 0; kk < BK; kk++) {
            F4U a0, a1;
            a0.f4 = *(const float4*)&As[kk][ty * 8];
            a1.f4 = *(const float4*)&As[kk][ty * 8 + 4];
            float4 bv0 = *(const float4*)&Bs[kk][tx * 8];
            float4 bv1 = *(const float4*)&Bs[kk][tx * 8 + 4];
            unsigned long long bd[8];
            bd[0] = pack2(bv0.x, bv0.x); bd[1] = pack2(bv0.y, bv0.y);
            bd[2] = pack2(bv0.z, bv0.z); bd[3] = pack2(bv0.w, bv0.w);
            bd[4] = pack2(bv1.x, bv1.x); bd[5] = pack2(bv1.y, bv1.y);
            bd[6] = pack2(bv1.z, bv1.z); bd[7] = pack2(bv1.w, bv1.w);
            unsigned long long ap[4] = { a0.u.lo, a0.u.hi, a1.u.lo, a1.u.hi };
#pragma unroll
            for (int i = 0; i < 4; i++)
#pragma unroll
                for (int j = 0; j < 8; j++)
                    fma_f32x2(acc[i][j], ap[i], bd[j]);
        }
        __syncthreads();
    }

    // epilogue: bias + relu, guarded stores
    float4 bb0 = *(const float4*)(bias + n0 + tx * 8);
    float4 bb1 = *(const float4*)(bias + n0 + tx * 8 + 4);
#pragma unroll
    for (int i2 = 0; i2 < 4; i2++) {
#pragma unroll
        for (int h = 0; h < 2; h++) {
            int m = m0 + ty * 8 + i2 * 2 + h;
            if (m < NN) {
                float2 c[8];
#pragma unroll
                for (int j = 0; j < 8; j++) {
                    F4U t; t.u.lo = acc[i2][j]; t.u.hi = 0;
                    c[j] = make_float2(t.f4.x, t.f4.y);
                }
                float4 v0, v1;
                v0.x = fmaxf((h ? c[0].y : c[0].x) + bb0.x, 0.f);
                v0.y = fmaxf((h ? c[1].y : c[1].x) + bb0.y, 0.f);
                v0.z = fmaxf((h ? c[2].y : c[2].x) + bb0.z, 0.f);
                v0.w = fmaxf((h ? c[3].y : c[3].x) + bb0.w, 0.f);
                v1.x = fmaxf((h ? c[4].y : c[4].x) + bb1.x, 0.f);
                v1.y = fmaxf((h ? c[5].y : c[5].x) + bb1.y, 0.f);
                v1.z = fmaxf((h ? c[6].y : c[6].x) + bb1.z, 0.f);
                v1.w = fmaxf((h ? c[7].y : c[7].x) + bb1.w, 0.f);
                *(float4*)(C + (size_t)m * HH + n0 + tx * 8)     = v0;
                *(float4*)(C + (size_t)m * HH + n0 + tx * 8 + 4) = v1;
            }
        }
    }
}

// ---------------- segmented pool: one block per graph ------------------------
__global__ void k_pool_seg(const float* __restrict__ in) {
    int g = blockIdx.x;
    int c = threadIdx.x;
    int lo = g_goff[g], hi = g_goff[g + 1];
    float acc = 0.0f;
    for (int n = lo; n < hi; n++) acc += in[(size_t)n * HH + c];
    g_sums[g * HH + c] = acc;
}

// ---------------- MLP head ----------------------------------------------------
__global__ void k_head(const float* __restrict__ na,
                       const float* __restrict__ W3, const float* __restrict__ b3,
                       const float* __restrict__ W4, const float* __restrict__ b4,
                       float* __restrict__ out) {
    int g = blockIdx.x;
    int j = threadIdx.x;   // 32 threads
    __shared__ float zsh[32];

    float cnt = (float)(g_goff[g + 1] - g_goff[g]);
    float inv = 1.0f / fmaxf(cnt, 1.0f);
    float acc = b3[j];
#pragma unroll 8
    for (int k = 0; k < HH; k++)
        acc += (g_sums[g * HH + k] * inv) * W3[k * 32 + j];
    acc += na[g] * W3[HH * 32 + j];
    zsh[j] = fmaxf(acc, 0.0f);
    __syncthreads();

    if (j < TT) {
        float o = b4[j];
#pragma unroll
        for (int t = 0; t < 32; t++) o += zsh[t] * W4[t * TT + j];
        out[g * TT + j] = o;
    }
}

// ---------------- launch -----------------------------------------------------
extern "C" void kernel_launch(void* const* d_in, const int* in_sizes, int n_in,
                              void* d_out, int out_size) {
    const float* x     = (const float*)d_in[0];
    const int*   ei    = (const int*)  d_in[1];
    const int*   batch = (const int*)  d_in[2];
    const float* na    = (const float*)d_in[3];
    const float* W1    = (const float*)d_in[4];
    const float* b1    = (const float*)d_in[5];
    const float* W2    = (const float*)d_in[6];
    const float* b2    = (const float*)d_in[7];
    const float* W3    = (const float*)d_in[8];
    const float* b3    = (const float*)d_in[9];
    const float* W4    = (const float*)d_in[10];
    const float* b4    = (const float*)d_in[11];
    float* out = (float*)d_out;

    // CSR build + normalization
    k_zero_counts<<<(NN + 255) / 256, 256>>>();
    k_deg<<<(EE + 255) / 256, 256>>>(ei);
    k_ghist<<<(NN + 255) / 256, 256>>>(batch);
    k_fin_dinv<<<(NN + 255) / 256, 256>>>();
    k_scan_nodes<<<1, 1024>>>();
    k_scan_graphs<<<1, GG>>>();
    k_scatter<<<(EE + 255) / 256, 256>>>(ei);

    const int agg_blocks = (NN * 32 + 255) / 256;
    dim3 gemm_grid(HH / 128, (NN + 127) / 128);

    // Layer 1: aggregate x (128-dim) first, then GEMM with fused bias+relu
    k_agg_csr<1><<<agg_blocks, 256>>>(x, g_buf2);
    k_gemm_f2<FF><<<gemm_grid, 256>>>(g_buf2, W1, b1, g_buf1);

    // Layer 2: aggregate h1 (256-dim), then GEMM with fused bias+relu
    k_agg_csr<2><<<agg_blocks, 256>>>(g_buf1, g_buf2);
    k_gemm_f2<HH><<<gemm_grid, 256>>>(g_buf2, W2, b2, g_buf1);

    // Pool + head
    k_pool_seg<<<GG, HH>>>(g_buf1);
    k_head<<<GG, 32>>>(na, W3, b3, W4, b4, out);
}

// round 9
// speedup vs baseline: 9.9045x; 9.7027x over previous
#include <cuda_runtime.h>
#include <cuda_bf16.h>

// Problem constants (fixed shapes for this problem instance)
#define NN 50000
#define EE 800000
#define FF 128
#define HH 256
#define GG 512
#define TT 4

// ---------------- scratch (device globals: no allocation allowed) ----------
__device__ __align__(16) float g_dinv[NN];
__device__ __align__(16) float g_buf1[(size_t)NN * HH];   // GEMM outputs
__device__ __align__(16) float g_buf2[(size_t)NN * HH];   // agg / activations
__device__ __align__(16) float g_sums[GG * HH];
__device__ float g_cnt[GG];

// ---------------- degree / normalization ----------------------------------
__global__ void k_init_dinv() {
    int n = blockIdx.x * blockDim.x + threadIdx.x;
    if (n < NN) g_dinv[n] = 1.0f;   // self-loop contributes 1 to degree
}

__global__ void k_deg(const int* __restrict__ ei) {
    int e = blockIdx.x * blockDim.x + threadIdx.x;
    if (e < EE) atomicAdd(&g_dinv[ei[EE + e]], 1.0f);   // dst row
}

__global__ void k_fin_dinv() {
    int n = blockIdx.x * blockDim.x + threadIdx.x;
    if (n < NN) g_dinv[n] = rsqrtf(g_dinv[n]);          // deg >= 1 always
}

// ---------------- zero kernels ---------------------------------------------
__global__ void k_zero_buf2() {
    int i = blockIdx.x * blockDim.x + threadIdx.x;
    int stride = gridDim.x * blockDim.x;
    float4* p = (float4*)g_buf2;
    const int n4 = (NN * HH) / 4;
    for (int j = i; j < n4; j += stride) p[j] = make_float4(0.f, 0.f, 0.f, 0.f);
}

__global__ void k_zero_pool() {
    int i = blockIdx.x * blockDim.x + threadIdx.x;
    if (i < GG * HH) g_sums[i] = 0.0f;
    if (i < GG) g_cnt[i] = 0.0f;
}

// ---------------- SGEMM: C[M,256] = A[M,K] @ B[K,256] ----------------------
// 64x64 tile, TK=16, 256 threads, 4x4 microtile per thread.
template<int K, bool SRC_BUF2>
__global__ void k_gemm(const float* __restrict__ Aarg, const float* __restrict__ B) {
    const float* __restrict__ A = SRC_BUF2 ? (const float*)g_buf2 : Aarg;
    float* __restrict__ C = g_buf1;

    __shared__ float As[16][64];
    __shared__ float Bs[16][64];

    const int tid = threadIdx.x;
    const int tx = tid & 15;
    const int ty = tid >> 4;
    const int m0 = blockIdx.y * 64;
    const int n0 = blockIdx.x * 64;

    float acc[4][4];
#pragma unroll
    for (int i = 0; i < 4; i++)
#pragma unroll
        for (int j = 0; j < 4; j++) acc[i][j] = 0.0f;

    const int ra = tid >> 2;          // 0..63  (A tile row)
    const int ca = (tid & 3) * 4;     // 0,4,8,12 (A tile k-offset)
    const int rb = tid >> 4;          // 0..15  (B tile row)
    const int cb = (tid & 15) * 4;    // 0..60  (B tile col)

    for (int k0 = 0; k0 < K; k0 += 16) {
        float4 av;
        if (m0 + ra < NN)
            av = *(const float4*)(A + (size_t)(m0 + ra) * K + k0 + ca);
        else
            av = make_float4(0.f, 0.f, 0.f, 0.f);
        As[ca + 0][ra] = av.x;
        As[ca + 1][ra] = av.y;
        As[ca + 2][ra] = av.z;
        As[ca + 3][ra] = av.w;

        *(float4*)&Bs[rb][cb] = *(const float4*)(B + (size_t)(k0 + rb) * HH + n0 + cb);

        __syncthreads();
#pragma unroll
        for (int k = 0; k < 16; k++) {
            float4 a = *(const float4*)&As[k][ty * 4];
            float4 b = *(const float4*)&Bs[k][tx * 4];
            acc[0][0] += a.x * b.x; acc[0][1] += a.x * b.y; acc[0][2] += a.x * b.z; acc[0][3] += a.x * b.w;
            acc[1][0] += a.y * b.x; acc[1][1] += a.y * b.y; acc[1][2] += a.y * b.z; acc[1][3] += a.y * b.w;
            acc[2][0] += a.z * b.x; acc[2][1] += a.z * b.y; acc[2][2] += a.z * b.z; acc[2][3] += a.z * b.w;
            acc[3][0] += a.w * b.x; acc[3][1] += a.w * b.y; acc[3][2] += a.w * b.z; acc[3][3] += a.w * b.w;
        }
        __syncthreads();
    }

#pragma unroll
    for (int i = 0; i < 4; i++) {
        int m = m0 + ty * 4 + i;
        if (m < NN) {
            float4 v = make_float4(acc[i][0], acc[i][1], acc[i][2], acc[i][3]);
            *(float4*)(C + (size_t)m * HH + n0 + tx * 4) = v;
        }
    }
}

// ---------------- edge aggregation: agg[dst] += h[src] * norm --------------
// One warp per edge; float4 vector atomics (sm_90+) keep us on the LTS byte cap.
__global__ void k_agg(const int* __restrict__ ei) {
    int w = (blockIdx.x * blockDim.x + threadIdx.x) >> 5;
    int lane = threadIdx.x & 31;
    if (w >= EE) return;
    int s = ei[w];
    int d = ei[EE + w];
    float nrm = g_dinv[s] * g_dinv[d];
    const float4* __restrict__ hs = (const float4*)(g_buf1 + (size_t)s * HH);
    float4* __restrict__ ad = (float4*)(g_buf2 + (size_t)d * HH);
#pragma unroll
    for (int i = 0; i < 2; i++) {
        int c = lane + i * 32;       // 0..63 float4s = 256 floats
        float4 v = hs[c];
        atomicAdd(&ad[c], make_float4(v.x * nrm, v.y * nrm, v.z * nrm, v.w * nrm));
    }
}

// ---------------- self-loop + bias + relu (in place into buf2) -------------
__global__ void k_post(const float* __restrict__ b) {
    int n = blockIdx.x;
    int c = threadIdx.x;
    float di = g_dinv[n];
    size_t idx = (size_t)n * HH + c;
    float v = g_buf2[idx] + g_buf1[idx] * (di * di) + b[c];
    g_buf2[idx] = fmaxf(v, 0.0f);
}

// ---------------- global mean pool -----------------------------------------
__global__ void k_pool(const int* __restrict__ batch) {
    int n = blockIdx.x;
    int c = threadIdx.x;
    int g = batch[n];
    atomicAdd(&g_sums[g * HH + c], g_buf2[(size_t)n * HH + c]);
    if (c == 0) atomicAdd(&g_cnt[g], 1.0f);
}

// ---------------- MLP head: relu(concat(pooled, na) @ W3 + b3) @ W4 + b4 ---
__global__ void k_head(const float* __restrict__ na,
                       const float* __restrict__ W3, const float* __restrict__ b3,
                       const float* __restrict__ W4, const float* __restrict__ b4,
                       float* __restrict__ out) {
    int g = blockIdx.x;
    int j = threadIdx.x;   // 32 threads, one per hidden unit
    __shared__ float zsh[32];

    float inv = 1.0f / fmaxf(g_cnt[g], 1.0f);
    float acc = b3[j];
#pragma unroll 8
    for (int k = 0; k < HH; k++)
        acc += (g_sums[g * HH + k] * inv) * W3[k * 32 + j];
    acc += na[g] * W3[HH * 32 + j];   // num_atoms feature (row 256 of W3)
    zsh[j] = fmaxf(acc, 0.0f);
    __syncthreads();

    if (j < TT) {
        float o = b4[j];
#pragma unroll
        for (int t = 0; t < 32; t++) o += zsh[t] * W4[t * TT + j];
        out[g * TT + j] = o;
    }
}

// ---------------- launch ----------------------------------------------------
extern "C" void kernel_launch(void* const* d_in, const int* in_sizes, int n_in,
                              void* d_out, int out_size) {
    const float* x     = (const float*)d_in[0];
    const int*   ei    = (const int*)  d_in[1];
    const int*   batch = (const int*)  d_in[2];
    const float* na    = (const float*)d_in[3];
    const float* W1    = (const float*)d_in[4];
    const float* b1    = (const float*)d_in[5];
    const float* W2    = (const float*)d_in[6];
    const float* b2    = (const float*)d_in[7];
    const float* W3    = (const float*)d_in[8];
    const float* b3    = (const float*)d_in[9];
    const float* W4    = (const float*)d_in[10];
    const float* b4    = (const float*)d_in[11];
    float* out = (float*)d_out;

    // degree -> dinv (idx 0-2)
    k_init_dinv<<<(NN + 255) / 256, 256>>>();
    k_deg<<<(EE + 255) / 256, 256>>>(ei);
    k_fin_dinv<<<(NN + 255) / 256, 256>>>();

    dim3 gemm_grid(HH / 64, (NN + 63) / 64);

    // idx 3: layer-1 GEMM — ncu profiles this launch
    k_gemm<FF, false><<<gemm_grid, 256>>>(x, W1);

    // Layer 1: zero ; agg ; relu(agg + selfloop + b1)
    k_zero_buf2<<<1024, 256>>>();
    k_agg<<<((size_t)EE * 32 + 255) / 256, 256>>>(ei);
    k_post<<<NN, 256>>>(b1);

    // Layer 2: h = a1 @ W2 ; zero ; agg ; relu(agg + selfloop + b2)
    k_gemm<HH, true><<<gemm_grid, 256>>>(nullptr, W2);
    k_zero_buf2<<<1024, 256>>>();
    k_agg<<<((size_t)EE * 32 + 255) / 256, 256>>>(ei);
    k_post<<<NN, 256>>>(b2);

    // Pool + head
    k_zero_pool<<<(GG * HH + 255) / 256, 256>>>();
    k_pool<<<NN, 256>>>(batch);
    k_head<<<GG, 32>>>(na, W3, b3, W4, b4, out);
}

// round 11
// speedup vs baseline: 10.0299x; 1.0127x over previous
#include <cuda_runtime.h>
#include <cuda_bf16.h>

// Problem constants (fixed shapes for this problem instance)
#define NN 50000
#define EE 800000
#define FF 128
#define HH 256
#define GG 512
#define TT 4

// ---------------- scratch (device globals: no allocation allowed) ----------
__device__ __align__(16) float g_dinv[NN];
__device__ __align__(16) float g_buf1[(size_t)NN * HH];   // GEMM outputs
__device__ __align__(16) float g_buf2[(size_t)NN * HH];   // agg / activations
__device__ __align__(16) float g_sums[GG * HH];
__device__ float g_cnt[GG];

// ---------------- degree / normalization ----------------------------------
__global__ void k_init_dinv() {
    int n = blockIdx.x * blockDim.x + threadIdx.x;
    if (n < NN) g_dinv[n] = 1.0f;   // self-loop contributes 1 to degree
}

__global__ void k_deg(const int* __restrict__ ei) {
    int e = blockIdx.x * blockDim.x + threadIdx.x;
    if (e < EE) atomicAdd(&g_dinv[ei[EE + e]], 1.0f);   // dst row
}

__global__ void k_fin_dinv() {
    int n = blockIdx.x * blockDim.x + threadIdx.x;
    if (n < NN) g_dinv[n] = rsqrtf(g_dinv[n]);          // deg >= 1 always
}

// ---------------- zero kernels ---------------------------------------------
__global__ void k_zero_buf2() {
    int i = blockIdx.x * blockDim.x + threadIdx.x;
    int stride = gridDim.x * blockDim.x;
    float4* p = (float4*)g_buf2;
    const int n4 = (NN * HH) / 4;
    for (int j = i; j < n4; j += stride) p[j] = make_float4(0.f, 0.f, 0.f, 0.f);
}

__global__ void k_zero_pool() {
    int i = blockIdx.x * blockDim.x + threadIdx.x;
    if (i < GG * HH) g_sums[i] = 0.0f;
    if (i < GG) g_cnt[i] = 0.0f;
}

// ---------------- SGEMM: C[M,256] = A[M,K] @ B[K,256] ----------------------
// 128x128 tile, BK=16, 256 threads, 8x8 microtile per thread.
// 64 B LDS per 64 FFMA per k-step (2x the arithmetic intensity of the old
// 4x4 version, which ncu showed pinned at L1=87.6% / fma=42.6%).
template<int K, bool SRC_BUF2>
__global__ void __launch_bounds__(256) k_gemm(const float* __restrict__ Aarg,
                                              const float* __restrict__ B) {
    const float* __restrict__ A = SRC_BUF2 ? (const float*)g_buf2 : Aarg;
    float* __restrict__ C = g_buf1;

    __shared__ float As[16][128];   // transposed: As[k][m]
    __shared__ float Bs[16][128];   // Bs[k][n]

    const int tid = threadIdx.x;
    const int tx = tid & 15;        // 16 col-groups of 8
    const int ty = tid >> 4;        // 16 row-groups of 8
    const int m0 = blockIdx.y * 128;
    const int n0 = blockIdx.x * 128;

    float acc[8][8];
#pragma unroll
    for (int i = 0; i < 8; i++)
#pragma unroll
        for (int j = 0; j < 8; j++) acc[i][j] = 0.0f;

    // loader mappings (each thread loads 2 float4 of A, 2 float4 of B)
    const int ra = tid >> 2;          // 0..63  (A row base; +64 on 2nd iter)
    const int ca = (tid & 3) * 4;     // k offset 0,4,8,12
    const int rb = tid >> 5;          // 0..7   (B row base; +8 on 2nd iter)
    const int cb = (tid & 31) * 4;    // col 0..124

    for (int k0 = 0; k0 < K; k0 += 16) {
#pragma unroll
        for (int it = 0; it < 2; it++) {
            int r = ra + it * 64;
            float4 av;
            if (m0 + r < NN)
                av = *(const float4*)(A + (size_t)(m0 + r) * K + k0 + ca);
            else
                av = make_float4(0.f, 0.f, 0.f, 0.f);
            As[ca + 0][r] = av.x;
            As[ca + 1][r] = av.y;
            As[ca + 2][r] = av.z;
            As[ca + 3][r] = av.w;
        }
#pragma unroll
        for (int it = 0; it < 2; it++) {
            int r = rb + it * 8;
            *(float4*)&Bs[r][cb] = *(const float4*)(B + (size_t)(k0 + r) * HH + n0 + cb);
        }
        __syncthreads();

#pragma unroll
        for (int k = 0; k < 16; k++) {
            float4 a0 = *(const float4*)&As[k][ty * 8];
            float4 a1 = *(const float4*)&As[k][ty * 8 + 4];
            float4 b0 = *(const float4*)&Bs[k][tx * 8];
            float4 b1 = *(const float4*)&Bs[k][tx * 8 + 4];
            float ar[8] = { a0.x, a0.y, a0.z, a0.w, a1.x, a1.y, a1.z, a1.w };
            float br[8] = { b0.x, b0.y, b0.z, b0.w, b1.x, b1.y, b1.z, b1.w };
#pragma unroll
            for (int i = 0; i < 8; i++)
#pragma unroll
                for (int j = 0; j < 8; j++)
                    acc[i][j] += ar[i] * br[j];
        }
        __syncthreads();
    }

#pragma unroll
    for (int i = 0; i < 8; i++) {
        int m = m0 + ty * 8 + i;
        if (m < NN) {
            float4 v0 = make_float4(acc[i][0], acc[i][1], acc[i][2], acc[i][3]);
            float4 v1 = make_float4(acc[i][4], acc[i][5], acc[i][6], acc[i][7]);
            *(float4*)(C + (size_t)m * HH + n0 + tx * 8)     = v0;
            *(float4*)(C + (size_t)m * HH + n0 + tx * 8 + 4) = v1;
        }
    }
}

// ---------------- edge aggregation: agg[dst] += h[src] * norm --------------
// One warp per edge; float4 vector atomics (sm_90+) keep us on the LTS byte cap.
__global__ void k_agg(const int* __restrict__ ei) {
    int w = (blockIdx.x * blockDim.x + threadIdx.x) >> 5;
    int lane = threadIdx.x & 31;
    if (w >= EE) return;
    int s = ei[w];
    int d = ei[EE + w];
    float nrm = g_dinv[s] * g_dinv[d];
    const float4* __restrict__ hs = (const float4*)(g_buf1 + (size_t)s * HH);
    float4* __restrict__ ad = (float4*)(g_buf2 + (size_t)d * HH);
#pragma unroll
    for (int i = 0; i < 2; i++) {
        int c = lane + i * 32;       // 0..63 float4s = 256 floats
        float4 v = hs[c];
        atomicAdd(&ad[c], make_float4(v.x * nrm, v.y * nrm, v.z * nrm, v.w * nrm));
    }
}

// ---------------- self-loop + bias + relu (in place into buf2) -------------
__global__ void k_post(const float* __restrict__ b) {
    int n = blockIdx.x;
    int c = threadIdx.x;
    float di = g_dinv[n];
    size_t idx = (size_t)n * HH + c;
    float v = g_buf2[idx] + g_buf1[idx] * (di * di) + b[c];
    g_buf2[idx] = fmaxf(v, 0.0f);
}

// ---------------- global mean pool -----------------------------------------
__global__ void k_pool(const int* __restrict__ batch) {
    int n = blockIdx.x;
    int c = threadIdx.x;
    int g = batch[n];
    atomicAdd(&g_sums[g * HH + c], g_buf2[(size_t)n * HH + c]);
    if (c == 0) atomicAdd(&g_cnt[g], 1.0f);
}

// ---------------- MLP head: relu(concat(pooled, na) @ W3 + b3) @ W4 + b4 ---
__global__ void k_head(const float* __restrict__ na,
                       const float* __restrict__ W3, const float* __restrict__ b3,
                       const float* __restrict__ W4, const float* __restrict__ b4,
                       float* __restrict__ out) {
    int g = blockIdx.x;
    int j = threadIdx.x;   // 32 threads, one per hidden unit
    __shared__ float zsh[32];

    float inv = 1.0f / fmaxf(g_cnt[g], 1.0f);
    float acc = b3[j];
#pragma unroll 8
    for (int k = 0; k < HH; k++)
        acc += (g_sums[g * HH + k] * inv) * W3[k * 32 + j];
    acc += na[g] * W3[HH * 32 + j];   // num_atoms feature (row 256 of W3)
    zsh[j] = fmaxf(acc, 0.0f);
    __syncthreads();

    if (j < TT) {
        float o = b4[j];
#pragma unroll
        for (int t = 0; t < 32; t++) o += zsh[t] * W4[t * TT + j];
        out[g * TT + j] = o;
    }
}

// ---------------- launch ----------------------------------------------------
extern "C" void kernel_launch(void* const* d_in, const int* in_sizes, int n_in,
                              void* d_out, int out_size) {
    const float* x     = (const float*)d_in[0];
    const int*   ei    = (const int*)  d_in[1];
    const int*   batch = (const int*)  d_in[2];
    const float* na    = (const float*)d_in[3];
    const float* W1    = (const float*)d_in[4];
    const float* b1    = (const float*)d_in[5];
    const float* W2    = (const float*)d_in[6];
    const float* b2    = (const float*)d_in[7];
    const float* W3    = (const float*)d_in[8];
    const float* b3    = (const float*)d_in[9];
    const float* W4    = (const float*)d_in[10];
    const float* b4    = (const float*)d_in[11];
    float* out = (float*)d_out;

    // degree -> dinv (idx 0-2)
    k_init_dinv<<<(NN + 255) / 256, 256>>>();
    k_deg<<<(EE + 255) / 256, 256>>>(ei);
    k_fin_dinv<<<(NN + 255) / 256, 256>>>();

    dim3 gemm_grid(HH / 128, (NN + 127) / 128);

    // idx 3: layer-1 GEMM — ncu profiles this launch
    k_gemm<FF, false><<<gemm_grid, 256>>>(x, W1);

    // Layer 1: zero ; agg ; relu(agg + selfloop + b1)
    k_zero_buf2<<<1024, 256>>>();
    k_agg<<<((size_t)EE * 32 + 255) / 256, 256>>>(ei);
    k_post<<<NN, 256>>>(b1);

    // Layer 2: h = a1 @ W2 ; zero ; agg ; relu(agg + selfloop + b2)
    k_gemm<HH, true><<<gemm_grid, 256>>>(nullptr, W2);
    k_zero_buf2<<<1024, 256>>>();
    k_agg<<<((size_t)EE * 32 + 255) / 256, 256>>>(ei);
    k_post<<<NN, 256>>>(b2);

    // Pool + head
    k_zero_pool<<<(GG * HH + 255) / 256, 256>>>();
    k_pool<<<NN, 256>>>(batch);
    k_head<<<GG, 32>>>(na, W3, b3, W4, b4, out);
}